// round 1
// baseline (speedup 1.0000x reference)
#include <cuda_runtime.h>
#include <cstddef>

#define NSIDE 512
#define MROWS (NSIDE*NSIDE)

// smem layout (in floats):
// [0,12288)      w1 x3 (f0,f10,f11), 4096 each   [64k x 64h, row-major]
// [12288,18432)  w2 x3, 2048 each                [64h x 32o, row-major]
// [18432,18624)  b1 x3, 64 each
// [18624,18720)  b2 x3, 32 each
#define SM_FLOATS 18720

struct Params {
  const float* x0;
  const float* x1;
  const float* rij;
  const float* w[12];   // f0: w1,b1,w2,b2 ; f10: ... ; f11: ...
  float* out;
};

__device__ __forceinline__ void radial_eval(const float (&x)[64],
                                            const float* __restrict__ sm,
                                            int f, float (&res)[32]) {
  const float* __restrict__ w1 = sm + f * 4096;
  const float* __restrict__ w2 = sm + 12288 + f * 2048;
  const float* __restrict__ b1 = sm + 18432 + f * 64;
  const float* __restrict__ b2 = sm + 18624 + f * 32;
  float oacc[32];
#pragma unroll
  for (int o = 0; o < 32; o++) oacc[o] = b2[o];
#pragma unroll
  for (int c = 0; c < 2; c++) {
    float acc[32];
#pragma unroll
    for (int h = 0; h < 32; h++) acc[h] = b1[c * 32 + h];
#pragma unroll 4
    for (int k = 0; k < 64; k++) {
      float xk = x[k];
      const float* wr = w1 + k * 64 + c * 32;
#pragma unroll
      for (int h = 0; h < 32; h++) acc[h] = fmaf(xk, wr[h], acc[h]);
    }
#pragma unroll 2
    for (int h = 0; h < 32; h++) {
      float a = fmaxf(acc[h], 0.0f);
      const float* wr = w2 + (c * 32 + h) * 32;
#pragma unroll
      for (int o = 0; o < 32; o++) oacc[o] = fmaf(a, wr[o], oacc[o]);
    }
  }
#pragma unroll
  for (int o = 0; o < 32; o++) res[o] = oacc[o];
}

__device__ __forceinline__ void store_vec96(float* __restrict__ dst,
                                            const float (&res)[32],
                                            float u0, float u1, float u2) {
  float4* d4 = (float4*)dst;
#pragma unroll
  for (int q = 0; q < 8; q++) {
    float a = res[4 * q + 0], b = res[4 * q + 1];
    float c = res[4 * q + 2], d = res[4 * q + 3];
    d4[3 * q + 0] = make_float4(a * u0, a * u1, a * u2, b * u0);
    d4[3 * q + 1] = make_float4(b * u1, b * u2, c * u0, c * u1);
    d4[3 * q + 2] = make_float4(c * u2, d * u0, d * u1, d * u2);
  }
}

__global__ void __launch_bounds__(128, 3) conv_kernel(Params p) {
  extern __shared__ float sm[];
  {
    const int tid = threadIdx.x;
    const int sizes[12] = {4096, 64, 2048, 32, 4096, 64, 2048, 32, 4096, 64, 2048, 32};
    const int dsts[12]  = {0, 18432, 12288, 18624,
                           4096, 18496, 14336, 18656,
                           8192, 18560, 16384, 18688};
#pragma unroll
    for (int fidx = 0; fidx < 12; fidx++) {
      const float* src = p.w[fidx];
      for (int i = tid; i < sizes[fidx]; i += 128) sm[dsts[fidx] + i] = src[i];
    }
  }
  __syncthreads();

  const int row = blockIdx.x * 128 + threadIdx.x;

  // unit vector + EPS mask from rij (match reference: dij = ||rij||, nrm = sqrt(max(d2, EPS)))
  const float* rp = p.rij + (size_t)row * 3;
  float r0 = rp[0], r1 = rp[1], r2 = rp[2];
  float d2 = r0 * r0 + r1 * r1 + r2 * r2;
  float dij = sqrtf(d2);
  float nrm = sqrtf(fmaxf(d2, 1e-8f));
  float u0, u1, u2;
  if (dij < 1e-8f) { u0 = u1 = u2 = 0.0f; }
  else { u0 = r0 / nrm; u1 = r1 / nrm; u2 = r2 / nrm; }

  float xr[64];
  float res[32];

  {
    const float4* xv = (const float4*)(p.x0 + (size_t)row * 64);
#pragma unroll
    for (int k = 0; k < 16; k++) {
      float4 v = xv[k];
      xr[4 * k] = v.x; xr[4 * k + 1] = v.y; xr[4 * k + 2] = v.z; xr[4 * k + 3] = v.w;
    }
  }

  // out0_a = radial_f0(x0)            @ elements [0, 32M)
  radial_eval(xr, sm, 0, res);
  {
    float4* d0 = (float4*)(p.out + (size_t)row * 32);
#pragma unroll
    for (int q = 0; q < 8; q++)
      d0[q] = make_float4(res[4 * q], res[4 * q + 1], res[4 * q + 2], res[4 * q + 3]);
  }

  // out1_a = filter1_f11(x0)          @ [64M, 160M)
  radial_eval(xr, sm, 2, res);
  store_vec96(p.out + (size_t)64 * MROWS + (size_t)row * 96, res, u0, u1, u2);

  {
    const float4* xv = (const float4*)(p.x1 + (size_t)row * 64);
#pragma unroll
    for (int k = 0; k < 16; k++) {
      float4 v = xv[k];
      xr[4 * k] = v.x; xr[4 * k + 1] = v.y; xr[4 * k + 2] = v.z; xr[4 * k + 3] = v.w;
    }
  }

  // out0_b = radial_f0(x1)            @ [32M, 64M)
  radial_eval(xr, sm, 0, res);
  {
    float4* d0 = (float4*)(p.out + (size_t)32 * MROWS + (size_t)row * 32);
#pragma unroll
    for (int q = 0; q < 8; q++)
      d0[q] = make_float4(res[4 * q], res[4 * q + 1], res[4 * q + 2], res[4 * q + 3]);
  }

  // out1_b = filter1_f10(x1)          @ [160M, 256M)
  radial_eval(xr, sm, 1, res);
  store_vec96(p.out + (size_t)160 * MROWS + (size_t)row * 96, res, u0, u1, u2);

  // out1_c = filter1_f11(x1)          @ [256M, 352M)
  radial_eval(xr, sm, 2, res);
  store_vec96(p.out + (size_t)256 * MROWS + (size_t)row * 96, res, u0, u1, u2);
}

extern "C" void kernel_launch(void* const* d_in, const int* in_sizes, int n_in,
                              void* d_out, int out_size) {
  Params p;
  p.x0  = (const float*)d_in[0];
  p.x1  = (const float*)d_in[1];
  // d_in[2] = rbf: unused by the reference computation
  p.rij = (const float*)d_in[3];
  for (int i = 0; i < 12; i++) p.w[i] = (const float*)d_in[4 + i];
  p.out = (float*)d_out;

  // 73.1 KB dynamic smem (> 48 KB default) — opt in every call (idempotent,
  // not a stream op, capture-safe).
  cudaFuncSetAttribute(conv_kernel, cudaFuncAttributeMaxDynamicSharedMemorySize,
                       SM_FLOATS * (int)sizeof(float));

  conv_kernel<<<MROWS / 128, 128, SM_FLOATS * sizeof(float)>>>(p);
}

// round 2
// speedup vs baseline: 1.4968x; 1.4968x over previous
#include <cuda_runtime.h>
#include <cstddef>

#define NSIDE 512
#define MROWS (NSIDE*NSIDE)

// smem layout (in floats):
// [0,12288)      w1 x3 (f0,f10,f11), 4096 each   [64k x 64h, row-major]
// [12288,18432)  w2 x3, 2048 each                [64h x 32o, row-major]
// [18432,18624)  b1 x3, 64 each
// [18624,18720)  b2 x3, 32 each
#define SM_FLOATS 18720

struct Params {
  const float* x0;
  const float* x1;
  const float* rij;
  const float* w[12];   // f0: w1,b1,w2,b2 ; f10: ... ; f11: ...
  float* out;
};

__device__ __forceinline__ void radial_eval(const float (&x)[64],
                                            const float* __restrict__ sm,
                                            int f, float (&res)[32]) {
  const float* __restrict__ w1 = sm + f * 4096;
  const float* __restrict__ w2 = sm + 12288 + f * 2048;
  const float* __restrict__ b1 = sm + 18432 + f * 64;
  const float* __restrict__ b2 = sm + 18624 + f * 32;
  float oacc[32];
#pragma unroll
  for (int o = 0; o < 32; o++) oacc[o] = b2[o];
#pragma unroll
  for (int c = 0; c < 2; c++) {
    float acc[32];
#pragma unroll
    for (int h = 0; h < 32; h++) acc[h] = b1[c * 32 + h];
    // k-loop: unroll 8 so the compiler can batch the broadcast LDS.128s well
    // ahead of the dependent FMA chains (hides 29-cyc LDS latency).
#pragma unroll 8
    for (int k = 0; k < 64; k++) {
      float xk = x[k];
      const float* wr = w1 + k * 64 + c * 32;
#pragma unroll
      for (int h = 0; h < 32; h++) acc[h] = fmaf(xk, wr[h], acc[h]);
    }
#pragma unroll 4
    for (int h = 0; h < 32; h++) {
      float a = fmaxf(acc[h], 0.0f);
      const float* wr = w2 + (c * 32 + h) * 32;
#pragma unroll
      for (int o = 0; o < 32; o++) oacc[o] = fmaf(a, wr[o], oacc[o]);
    }
  }
#pragma unroll
  for (int o = 0; o < 32; o++) res[o] = oacc[o];
}

__device__ __forceinline__ void store_vec96(float* __restrict__ dst,
                                            const float (&res)[32],
                                            float u0, float u1, float u2) {
  float4* d4 = (float4*)dst;
#pragma unroll
  for (int q = 0; q < 8; q++) {
    float a = res[4 * q + 0], b = res[4 * q + 1];
    float c = res[4 * q + 2], d = res[4 * q + 3];
    d4[3 * q + 0] = make_float4(a * u0, a * u1, a * u2, b * u0);
    d4[3 * q + 1] = make_float4(b * u1, b * u2, c * u0, c * u1);
    d4[3 * q + 2] = make_float4(c * u2, d * u0, d * u1, d * u2);
  }
}

// 2 blocks/SM: 255-reg budget -> NO spills (round-1 config capped at 170 and
// spilled, putting LDL/STL in the hot loops; L1TEX was 62% busy on spill
// traffic). smem allows only 2 blocks/SM anyway (2 x 73KB <= 227KB).
__global__ void __launch_bounds__(128, 2) conv_kernel(Params p) {
  extern __shared__ float sm[];
  {
    const int tid = threadIdx.x;
    const int sizes[12] = {4096, 64, 2048, 32, 4096, 64, 2048, 32, 4096, 64, 2048, 32};
    const int dsts[12]  = {0, 18432, 12288, 18624,
                           4096, 18496, 14336, 18656,
                           8192, 18560, 16384, 18688};
#pragma unroll
    for (int fidx = 0; fidx < 12; fidx++) {
      const float* src = p.w[fidx];
      for (int i = tid; i < sizes[fidx]; i += 128) sm[dsts[fidx] + i] = src[i];
    }
  }
  __syncthreads();

  const int row = blockIdx.x * 128 + threadIdx.x;

  // unit vector + EPS mask from rij (match reference: dij = ||rij||, nrm = sqrt(max(d2, EPS)))
  const float* rp = p.rij + (size_t)row * 3;
  float r0 = rp[0], r1 = rp[1], r2 = rp[2];
  float d2 = r0 * r0 + r1 * r1 + r2 * r2;
  float dij = sqrtf(d2);
  float nrm = sqrtf(fmaxf(d2, 1e-8f));
  float u0, u1, u2;
  if (dij < 1e-8f) { u0 = u1 = u2 = 0.0f; }
  else { u0 = r0 / nrm; u1 = r1 / nrm; u2 = r2 / nrm; }

  float xr[64];
  float res[32];

  {
    const float4* xv = (const float4*)(p.x0 + (size_t)row * 64);
#pragma unroll
    for (int k = 0; k < 16; k++) {
      float4 v = xv[k];
      xr[4 * k] = v.x; xr[4 * k + 1] = v.y; xr[4 * k + 2] = v.z; xr[4 * k + 3] = v.w;
    }
  }

  // out0_a = radial_f0(x0)            @ elements [0, 32M)
  radial_eval(xr, sm, 0, res);
  {
    float4* d0 = (float4*)(p.out + (size_t)row * 32);
#pragma unroll
    for (int q = 0; q < 8; q++)
      d0[q] = make_float4(res[4 * q], res[4 * q + 1], res[4 * q + 2], res[4 * q + 3]);
  }

  // out1_a = filter1_f11(x0)          @ [64M, 160M)
  radial_eval(xr, sm, 2, res);
  store_vec96(p.out + (size_t)64 * MROWS + (size_t)row * 96, res, u0, u1, u2);

  {
    const float4* xv = (const float4*)(p.x1 + (size_t)row * 64);
#pragma unroll
    for (int k = 0; k < 16; k++) {
      float4 v = xv[k];
      xr[4 * k] = v.x; xr[4 * k + 1] = v.y; xr[4 * k + 2] = v.z; xr[4 * k + 3] = v.w;
    }
  }

  // out0_b = radial_f0(x1)            @ [32M, 64M)
  radial_eval(xr, sm, 0, res);
  {
    float4* d0 = (float4*)(p.out + (size_t)32 * MROWS + (size_t)row * 32);
#pragma unroll
    for (int q = 0; q < 8; q++)
      d0[q] = make_float4(res[4 * q], res[4 * q + 1], res[4 * q + 2], res[4 * q + 3]);
  }

  // out1_b = filter1_f10(x1)          @ [160M, 256M)
  radial_eval(xr, sm, 1, res);
  store_vec96(p.out + (size_t)160 * MROWS + (size_t)row * 96, res, u0, u1, u2);

  // out1_c = filter1_f11(x1)          @ [256M, 352M)
  radial_eval(xr, sm, 2, res);
  store_vec96(p.out + (size_t)256 * MROWS + (size_t)row * 96, res, u0, u1, u2);
}

extern "C" void kernel_launch(void* const* d_in, const int* in_sizes, int n_in,
                              void* d_out, int out_size) {
  Params p;
  p.x0  = (const float*)d_in[0];
  p.x1  = (const float*)d_in[1];
  // d_in[2] = rbf: unused by the reference computation
  p.rij = (const float*)d_in[3];
  for (int i = 0; i < 12; i++) p.w[i] = (const float*)d_in[4 + i];
  p.out = (float*)d_out;

  // 73.1 KB dynamic smem (> 48 KB default) — opt in every call (idempotent,
  // not a stream op, capture-safe).
  cudaFuncSetAttribute(conv_kernel, cudaFuncAttributeMaxDynamicSharedMemorySize,
                       SM_FLOATS * (int)sizeof(float));

  conv_kernel<<<MROWS / 128, 128, SM_FLOATS * sizeof(float)>>>(p);
}

// round 5
// speedup vs baseline: 3.1563x; 2.1087x over previous
#include <cuda_runtime.h>
#include <cuda_bf16.h>
#include <cstdint>
#include <cstddef>

#define MROWS (512*512)
#define NTILES 2048
#define GRID 296
#define NTH 256

// ---------------- smem layout (bytes) ----------------
// SB1: stage-1 B fragments uint32[3 filters][8 ntile][4 kstep][2 half][32 lane][2 reg]
// SB2: stage-2 B fragments uint32[3][4][4][2][32][2]
// B1S: biases b1 [3][64], B2S: b2 [3][32]
// U:   unit vectors, double-buffered [2][128][4]
#define OFF_SB1 0u
#define OFF_SB2 49152u
#define OFF_B1  73728u
#define OFF_B2  74496u
#define OFF_U   74880u
#define SMEM_BYTES 78976u

struct Params {
  const float* x0;
  const float* x1;
  const float* rij;
  const float* w[12];   // f0: w1,b1,w2,b2 ; f10: ... ; f11: ...
  float* out;
};

// mma.sync m16n8k16 row.col f32.bf16.bf16.f32  (non-'a' feature: valid at compute_103)
__device__ __forceinline__ void mma16816(float (&c)[4], const uint32_t (&a)[4],
                                         uint32_t b0, uint32_t b1) {
  asm volatile(
      "mma.sync.aligned.m16n8k16.row.col.f32.bf16.bf16.f32 "
      "{%0,%1,%2,%3}, {%4,%5,%6,%7}, {%8,%9}, {%0,%1,%2,%3};"
      : "+f"(c[0]), "+f"(c[1]), "+f"(c[2]), "+f"(c[3])
      : "r"(a[0]), "r"(a[1]), "r"(a[2]), "r"(a[3]), "r"(b0), "r"(b1));
}

// split v into bf16 hi (returned packed) and bf16 lo (packed via out-param)
__device__ __forceinline__ uint32_t pack_split(float vx, float vy, uint32_t& lo) {
  __nv_bfloat162 h = __float22bfloat162_rn(make_float2(vx, vy));
  float2 hf = __bfloat1622float2(h);
  __nv_bfloat162 l = __float22bfloat162_rn(make_float2(vx - hf.x, vy - hf.y));
  lo = *reinterpret_cast<uint32_t*>(&l);
  return *reinterpret_cast<uint32_t*>(&h);
}

__device__ __forceinline__ __nv_bfloat16 bf_part(float v, int h) {
  __nv_bfloat16 hi = __float2bfloat16_rn(v);
  if (h == 0) return hi;
  return __float2bfloat16_rn(v - __bfloat162float(hi));
}

// one (x, filter) combo: stage1 [16x64] -> relu -> stage2 [16x32] -> epilogue.
// Entirely warp-local.
__device__ __forceinline__ void run_combo(
    const uint32_t (&Ah)[4][4], const uint32_t (&Al)[4][4], int f,
    const uint32_t* __restrict__ sb1l, const uint32_t* __restrict__ sb2l,
    const float* __restrict__ B1s, const float* __restrict__ B2s,
    const float* __restrict__ ub, int ro, int g, int t,
    float* __restrict__ outp, int rowbase, bool vec) {
  // ---- stage 1: C1[16 x 64] over 8 n-tiles ----
  float C1[8][4];
#pragma unroll
  for (int j = 0; j < 8; j++) {
    C1[j][0] = 0.f; C1[j][1] = 0.f; C1[j][2] = 0.f; C1[j][3] = 0.f;
  }
#pragma unroll
  for (int j = 0; j < 8; j++) {
#pragma unroll
    for (int s = 0; s < 4; s++) {
      int off = (((f * 8 + j) * 4 + s) * 2) * 64;
      uint2 bh = *(const uint2*)(sb1l + off);
      uint2 bl = *(const uint2*)(sb1l + off + 64);
      mma16816(C1[j], Ah[s], bh.x, bh.y);
      mma16816(C1[j], Al[s], bh.x, bh.y);
      mma16816(C1[j], Ah[s], bl.x, bl.y);
    }
  }
  // ---- bias + relu ----
  const float* b1f = B1s + f * 64;
#pragma unroll
  for (int j = 0; j < 8; j++) {
    float2 b = *(const float2*)(b1f + 8 * j + 2 * t);
    C1[j][0] = fmaxf(C1[j][0] + b.x, 0.f);
    C1[j][1] = fmaxf(C1[j][1] + b.y, 0.f);
    C1[j][2] = fmaxf(C1[j][2] + b.x, 0.f);
    C1[j][3] = fmaxf(C1[j][3] + b.y, 0.f);
  }
  // ---- C1 fragments -> stage-2 A fragments (register-only; layouts match) ----
  uint32_t A2h[4][4], A2l[4][4];
#pragma unroll
  for (int s2 = 0; s2 < 4; s2++) {
    A2h[s2][0] = pack_split(C1[2 * s2][0],     C1[2 * s2][1],     A2l[s2][0]);
    A2h[s2][1] = pack_split(C1[2 * s2][2],     C1[2 * s2][3],     A2l[s2][1]);
    A2h[s2][2] = pack_split(C1[2 * s2 + 1][0], C1[2 * s2 + 1][1], A2l[s2][2]);
    A2h[s2][3] = pack_split(C1[2 * s2 + 1][2], C1[2 * s2 + 1][3], A2l[s2][3]);
  }
  // ---- stage 2: C2[16 x 32] over 4 n-tiles ----
  float C2[4][4];
#pragma unroll
  for (int j = 0; j < 4; j++) {
    C2[j][0] = 0.f; C2[j][1] = 0.f; C2[j][2] = 0.f; C2[j][3] = 0.f;
  }
#pragma unroll
  for (int j2 = 0; j2 < 4; j2++) {
#pragma unroll
    for (int s2 = 0; s2 < 4; s2++) {
      int off = (((f * 4 + j2) * 4 + s2) * 2) * 64;
      uint2 bh = *(const uint2*)(sb2l + off);
      uint2 bl = *(const uint2*)(sb2l + off + 64);
      mma16816(C2[j2], A2h[s2], bh.x, bh.y);
      mma16816(C2[j2], A2l[s2], bh.x, bh.y);
      mma16816(C2[j2], A2h[s2], bl.x, bl.y);
    }
  }
  // ---- epilogue ----
  const float* b2f = B2s + f * 32;
  if (!vec) {
    float* r0p = outp + (size_t)(rowbase + g) * 32;
    float* r1p = outp + (size_t)(rowbase + g + 8) * 32;
#pragma unroll
    for (int j2 = 0; j2 < 4; j2++) {
      float2 b = *(const float2*)(b2f + 8 * j2 + 2 * t);
      int col = 8 * j2 + 2 * t;
      *(float2*)(r0p + col) = make_float2(C2[j2][0] + b.x, C2[j2][1] + b.y);
      *(float2*)(r1p + col) = make_float2(C2[j2][2] + b.x, C2[j2][3] + b.y);
    }
  } else {
    // u vectors indexed by row within the 128-row tile: ro and ro+8
    // (round-4 bug: used g / g+8, i.e. every warp read warp-0's rows)
    const float* u0p = ub + ro * 4;
    const float* u1p = ub + (ro + 8) * 4;
    float ua0 = u0p[0], ua1 = u0p[1], ua2 = u0p[2];
    float ub0 = u1p[0], ub1 = u1p[1], ub2 = u1p[2];
    float* r0p = outp + (size_t)(rowbase + g) * 96;
    float* r1p = outp + (size_t)(rowbase + g + 8) * 96;
#pragma unroll
    for (int j2 = 0; j2 < 4; j2++) {
      float2 b = *(const float2*)(b2f + 8 * j2 + 2 * t);
      int col3 = (8 * j2 + 2 * t) * 3;
      float v0 = C2[j2][0] + b.x, v1 = C2[j2][1] + b.y;
      r0p[col3 + 0] = v0 * ua0; r0p[col3 + 1] = v0 * ua1; r0p[col3 + 2] = v0 * ua2;
      r0p[col3 + 3] = v1 * ua0; r0p[col3 + 4] = v1 * ua1; r0p[col3 + 5] = v1 * ua2;
      float w0 = C2[j2][2] + b.x, w1 = C2[j2][3] + b.y;
      r1p[col3 + 0] = w0 * ub0; r1p[col3 + 1] = w0 * ub1; r1p[col3 + 2] = w0 * ub2;
      r1p[col3 + 3] = w1 * ub0; r1p[col3 + 4] = w1 * ub1; r1p[col3 + 5] = w1 * ub2;
    }
  }
}

// load x tile rows for this warp directly from gmem into A fragments (hi/lo bf16)
__device__ __forceinline__ void load_xfrags(const float* __restrict__ x, int row0,
                                            int ro, int t,
                                            uint32_t (&Ah)[4][4], uint32_t (&Al)[4][4]) {
  const float* base = x + (size_t)(row0 + ro) * 64 + 2 * t;
#pragma unroll
  for (int s = 0; s < 4; s++) {
    const float* bs = base + 16 * s;
    float2 v0 = __ldg((const float2*)(bs));            // row g,   k 16s+2t
    float2 v1 = __ldg((const float2*)(bs + 8 * 64));   // row g+8, k 16s+2t
    float2 v2 = __ldg((const float2*)(bs + 8));        // row g,   k 16s+2t+8
    float2 v3 = __ldg((const float2*)(bs + 8 * 64 + 8));
    Ah[s][0] = pack_split(v0.x, v0.y, Al[s][0]);
    Ah[s][1] = pack_split(v1.x, v1.y, Al[s][1]);
    Ah[s][2] = pack_split(v2.x, v2.y, Al[s][2]);
    Ah[s][3] = pack_split(v3.x, v3.y, Al[s][3]);
  }
}

__global__ void __launch_bounds__(NTH) conv_mma(Params p) {
  extern __shared__ char sm[];
  uint32_t* SB1 = (uint32_t*)(sm + OFF_SB1);
  uint32_t* SB2 = (uint32_t*)(sm + OFF_SB2);
  float* B1s = (float*)(sm + OFF_B1);
  float* B2s = (float*)(sm + OFF_B2);
  float* U   = (float*)(sm + OFF_U);

  const int tid = threadIdx.x;

  // ---- one-time: build B fragments in exact mma per-lane order ----
  // filter order: 0=f0 (w[0..3]), 1=f11 (w[8..11]), 2=f10 (w[4..7])
  for (int idx = tid; idx < 12288; idx += NTH) {
    int i = idx;
    int r = i & 1; i >>= 1;
    int lane = i & 31; i >>= 5;
    int h = i & 1; i >>= 1;
    int s = i & 3; i >>= 2;
    int j = i & 7; i >>= 3;
    int f = i;
    int g = lane >> 2, t = lane & 3;
    int n = 8 * j + g;
    int kb = 16 * s + 2 * t + 8 * r;
    const float* w1 = (f == 0) ? p.w[0] : (f == 1) ? p.w[8] : p.w[4];
    float v0 = __ldg(w1 + kb * 64 + n);
    float v1 = __ldg(w1 + (kb + 1) * 64 + n);
    __nv_bfloat162 pk;
    pk.x = bf_part(v0, h);
    pk.y = bf_part(v1, h);
    SB1[idx] = *reinterpret_cast<uint32_t*>(&pk);
  }
  for (int idx = tid; idx < 6144; idx += NTH) {
    int i = idx;
    int r = i & 1; i >>= 1;
    int lane = i & 31; i >>= 5;
    int h = i & 1; i >>= 1;
    int s = i & 3; i >>= 2;
    int j = i & 3; i >>= 2;
    int f = i;
    int g = lane >> 2, t = lane & 3;
    int n = 8 * j + g;
    int kb = 16 * s + 2 * t + 8 * r;
    const float* w2 = (f == 0) ? p.w[2] : (f == 1) ? p.w[10] : p.w[6];
    float v0 = __ldg(w2 + kb * 32 + n);
    float v1 = __ldg(w2 + (kb + 1) * 32 + n);
    __nv_bfloat162 pk;
    pk.x = bf_part(v0, h);
    pk.y = bf_part(v1, h);
    SB2[idx] = *reinterpret_cast<uint32_t*>(&pk);
  }
  for (int n = tid; n < 192; n += NTH) {
    const float* b1 = (n < 64) ? p.w[1] : (n < 128) ? p.w[9] : p.w[5];
    B1s[n] = __ldg(b1 + (n & 63));
  }
  for (int n = tid; n < 96; n += NTH) {
    const float* b2 = (n < 32) ? p.w[3] : (n < 64) ? p.w[11] : p.w[7];
    B2s[n] = __ldg(b2 + (n & 31));
  }
  __syncthreads();

  const int w = tid >> 5, lane = tid & 31;
  const int g = lane >> 2, t = lane & 3;
  const int ro = w * 16 + g;            // warp row offset within tile (+g)
  const uint32_t* sb1l = SB1 + lane * 2;
  const uint32_t* sb2l = SB2 + lane * 2;

  float* const o0a = p.out;
  float* const o0b = p.out + (size_t)32 * MROWS;
  float* const o1a = p.out + (size_t)64 * MROWS;
  float* const o1b = p.out + (size_t)160 * MROWS;
  float* const o1c = p.out + (size_t)256 * MROWS;

  for (int tile = blockIdx.x; tile < NTILES; tile += GRID) {
    const int row0 = tile << 7;
    float* ubuf = U + (size_t)(tile & 1) * 512;
    if (tid < 128) {
      const float* rp = p.rij + (size_t)(row0 + tid) * 3;
      float r0 = rp[0], r1 = rp[1], r2 = rp[2];
      float d2 = r0 * r0 + r1 * r1 + r2 * r2;
      float dij = sqrtf(d2);
      float nrm = sqrtf(fmaxf(d2, 1e-8f));
      float* uu = ubuf + tid * 4;
      if (dij < 1e-8f) { uu[0] = 0.f; uu[1] = 0.f; uu[2] = 0.f; }
      else { uu[0] = r0 / nrm; uu[1] = r1 / nrm; uu[2] = r2 / nrm; }
    }
    __syncthreads();

    uint32_t Ah[4][4], Al[4][4];
    const int rowbase = row0 + w * 16;

    // x0: f0 -> out0_a (plain), f11 -> out1_a (vec)
    load_xfrags(p.x0, row0, ro, t, Ah, Al);
    run_combo(Ah, Al, 0, sb1l, sb2l, B1s, B2s, ubuf, ro, g, t, o0a, rowbase, false);
    run_combo(Ah, Al, 1, sb1l, sb2l, B1s, B2s, ubuf, ro, g, t, o1a, rowbase, true);

    // x1: f0 -> out0_b (plain), f10 -> out1_b (vec), f11 -> out1_c (vec)
    load_xfrags(p.x1, row0, ro, t, Ah, Al);
    run_combo(Ah, Al, 0, sb1l, sb2l, B1s, B2s, ubuf, ro, g, t, o0b, rowbase, false);
    run_combo(Ah, Al, 2, sb1l, sb2l, B1s, B2s, ubuf, ro, g, t, o1b, rowbase, true);
    run_combo(Ah, Al, 1, sb1l, sb2l, B1s, B2s, ubuf, ro, g, t, o1c, rowbase, true);
  }
}

extern "C" void kernel_launch(void* const* d_in, const int* in_sizes, int n_in,
                              void* d_out, int out_size) {
  Params p;
  p.x0  = (const float*)d_in[0];
  p.x1  = (const float*)d_in[1];
  // d_in[2] = rbf: unused by the reference computation
  p.rij = (const float*)d_in[3];
  for (int i = 0; i < 12; i++) p.w[i] = (const float*)d_in[4 + i];
  p.out = (float*)d_out;

  cudaFuncSetAttribute(conv_mma, cudaFuncAttributeMaxDynamicSharedMemorySize, SMEM_BYTES);
  conv_mma<<<GRID, NTH, SMEM_BYTES>>>(p);
}

// round 8
// speedup vs baseline: 3.8819x; 1.2299x over previous
#include <cuda_runtime.h>
#include <cuda_bf16.h>
#include <cstdint>
#include <cstddef>

#define MROWS (512*512)
#define NTILES 2048
#define GRID 296
#define NTH 128

// ---------------- smem layout (bytes) ----------------
// SB1: stage-1 B fragments uint32[3 f][8 j][4 s][32 lane][4 q]  q={hi0,hi1,lo0,lo1}
// SB2: stage-2 B fragments uint32[3][4][4][32][4]
// B1S/B2S: biases. U: unit vectors double-buffered [2][128][4].
#define OFF_SB1 0u
#define OFF_SB2 49152u
#define OFF_B1  73728u
#define OFF_B2  74496u
#define OFF_U   74880u
#define SMEM_BYTES 78976u

struct Params {
  const float* x0;
  const float* x1;
  const float* rij;
  const float* w[12];   // f0: w1,b1,w2,b2 ; f10: ... ; f11: ...
  float* out;
};

__device__ __forceinline__ void mma16816(float (&c)[4], const uint32_t (&a)[4],
                                         uint32_t b0, uint32_t b1) {
  asm volatile(
      "mma.sync.aligned.m16n8k16.row.col.f32.bf16.bf16.f32 "
      "{%0,%1,%2,%3}, {%4,%5,%6,%7}, {%8,%9}, {%0,%1,%2,%3};"
      : "+f"(c[0]), "+f"(c[1]), "+f"(c[2]), "+f"(c[3])
      : "r"(a[0]), "r"(a[1]), "r"(a[2]), "r"(a[3]), "r"(b0), "r"(b1));
}

__device__ __forceinline__ uint32_t pack_split(float vx, float vy, uint32_t& lo) {
  __nv_bfloat162 h = __float22bfloat162_rn(make_float2(vx, vy));
  float2 hf = __bfloat1622float2(h);
  __nv_bfloat162 l = __float22bfloat162_rn(make_float2(vx - hf.x, vy - hf.y));
  lo = *reinterpret_cast<uint32_t*>(&l);
  return *reinterpret_cast<uint32_t*>(&h);
}

__device__ __forceinline__ __nv_bfloat16 bf_part(float v, int h) {
  __nv_bfloat16 hi = __float2bfloat16_rn(v);
  if (h == 0) return hi;
  return __float2bfloat16_rn(v - __bfloat162float(hi));
}

// ---- proven round-5 scatter epilogues ----
__device__ __forceinline__ void epi_plain(const float (&C2)[4][4], int g, int t,
                                          float* __restrict__ outp, int rowbase) {
  float* r0p = outp + (size_t)(rowbase + g) * 32;
  float* r1p = outp + (size_t)(rowbase + g + 8) * 32;
#pragma unroll
  for (int j2 = 0; j2 < 4; j2++) {
    int col = 8 * j2 + 2 * t;
    *(float2*)(r0p + col) = make_float2(C2[j2][0], C2[j2][1]);
    *(float2*)(r1p + col) = make_float2(C2[j2][2], C2[j2][3]);
  }
}

__device__ __forceinline__ void epi_vec(const float (&C2)[4][4],
                                        const float* __restrict__ ub,
                                        int ro, int g, int t,
                                        float* __restrict__ outp, int rowbase) {
  const float* u0p = ub + ro * 4;
  const float* u1p = ub + (ro + 8) * 4;
  float ua0 = u0p[0], ua1 = u0p[1], ua2 = u0p[2];
  float ub0 = u1p[0], ub1 = u1p[1], ub2 = u1p[2];
  float* r0p = outp + (size_t)(rowbase + g) * 96;
  float* r1p = outp + (size_t)(rowbase + g + 8) * 96;
#pragma unroll
  for (int j2 = 0; j2 < 4; j2++) {
    int col3 = (8 * j2 + 2 * t) * 3;
    float v0 = C2[j2][0], v1 = C2[j2][1];
    r0p[col3 + 0] = v0 * ua0; r0p[col3 + 1] = v0 * ua1; r0p[col3 + 2] = v0 * ua2;
    r0p[col3 + 3] = v1 * ua0; r0p[col3 + 4] = v1 * ua1; r0p[col3 + 5] = v1 * ua2;
    float w0 = C2[j2][2], w1 = C2[j2][3];
    r1p[col3 + 0] = w0 * ub0; r1p[col3 + 1] = w0 * ub1; r1p[col3 + 2] = w0 * ub2;
    r1p[col3 + 3] = w1 * ub0; r1p[col3 + 4] = w1 * ub1; r1p[col3 + 5] = w1 * ub2;
  }
}

// dual-slice combo: both slices share every B-fragment load; two independent
// MMA chains per warp (2x ILP). stage1 -> relu -> stage2 -> epilogue per slice.
__device__ __forceinline__ void run_pair(
    const uint32_t (&Ah0)[4][4], const uint32_t (&Al0)[4][4],
    const uint32_t (&Ah1)[4][4], const uint32_t (&Al1)[4][4], int f,
    const uint32_t* __restrict__ sb1l4, const uint32_t* __restrict__ sb2l4,
    const float* __restrict__ B1s, const float* __restrict__ B2s,
    const float* __restrict__ ub, int ro, int g, int t,
    float* __restrict__ outp, int rowbase, bool vec) {
  // ---- stage 1 (dual) ----
  float C1a[8][4], C1b[8][4];
#pragma unroll
  for (int j = 0; j < 8; j++)
#pragma unroll
    for (int e = 0; e < 4; e++) { C1a[j][e] = 0.f; C1b[j][e] = 0.f; }
#pragma unroll
  for (int j = 0; j < 8; j++) {
#pragma unroll
    for (int s = 0; s < 4; s++) {
      uint4 bb = *(const uint4*)(sb1l4 + ((f * 8 + j) * 4 + s) * 128);
      mma16816(C1a[j], Ah0[s], bb.x, bb.y);
      mma16816(C1b[j], Ah1[s], bb.x, bb.y);
      mma16816(C1a[j], Al0[s], bb.x, bb.y);
      mma16816(C1b[j], Al1[s], bb.x, bb.y);
      mma16816(C1a[j], Ah0[s], bb.z, bb.w);
      mma16816(C1b[j], Ah1[s], bb.z, bb.w);
    }
  }
  // ---- bias + relu ----
  const float* b1f = B1s + f * 64;
#pragma unroll
  for (int j = 0; j < 8; j++) {
    float2 b = *(const float2*)(b1f + 8 * j + 2 * t);
    C1a[j][0] = fmaxf(C1a[j][0] + b.x, 0.f);
    C1a[j][1] = fmaxf(C1a[j][1] + b.y, 0.f);
    C1a[j][2] = fmaxf(C1a[j][2] + b.x, 0.f);
    C1a[j][3] = fmaxf(C1a[j][3] + b.y, 0.f);
    C1b[j][0] = fmaxf(C1b[j][0] + b.x, 0.f);
    C1b[j][1] = fmaxf(C1b[j][1] + b.y, 0.f);
    C1b[j][2] = fmaxf(C1b[j][2] + b.x, 0.f);
    C1b[j][3] = fmaxf(C1b[j][3] + b.y, 0.f);
  }
  // ---- C1 -> stage-2 A fragments (register-only) ----
  uint32_t A2h0[4][4], A2l0[4][4], A2h1[4][4], A2l1[4][4];
#pragma unroll
  for (int s2 = 0; s2 < 4; s2++) {
    A2h0[s2][0] = pack_split(C1a[2 * s2][0],     C1a[2 * s2][1],     A2l0[s2][0]);
    A2h0[s2][1] = pack_split(C1a[2 * s2][2],     C1a[2 * s2][3],     A2l0[s2][1]);
    A2h0[s2][2] = pack_split(C1a[2 * s2 + 1][0], C1a[2 * s2 + 1][1], A2l0[s2][2]);
    A2h0[s2][3] = pack_split(C1a[2 * s2 + 1][2], C1a[2 * s2 + 1][3], A2l0[s2][3]);
    A2h1[s2][0] = pack_split(C1b[2 * s2][0],     C1b[2 * s2][1],     A2l1[s2][0]);
    A2h1[s2][1] = pack_split(C1b[2 * s2][2],     C1b[2 * s2][3],     A2l1[s2][1]);
    A2h1[s2][2] = pack_split(C1b[2 * s2 + 1][0], C1b[2 * s2 + 1][1], A2l1[s2][2]);
    A2h1[s2][3] = pack_split(C1b[2 * s2 + 1][2], C1b[2 * s2 + 1][3], A2l1[s2][3]);
  }
  // ---- stage 2 (dual) ----
  float C2a[4][4], C2b[4][4];
#pragma unroll
  for (int j = 0; j < 4; j++)
#pragma unroll
    for (int e = 0; e < 4; e++) { C2a[j][e] = 0.f; C2b[j][e] = 0.f; }
#pragma unroll
  for (int j2 = 0; j2 < 4; j2++) {
#pragma unroll
    for (int s2 = 0; s2 < 4; s2++) {
      uint4 bb = *(const uint4*)(sb2l4 + ((f * 4 + j2) * 4 + s2) * 128);
      mma16816(C2a[j2], A2h0[s2], bb.x, bb.y);
      mma16816(C2b[j2], A2h1[s2], bb.x, bb.y);
      mma16816(C2a[j2], A2l0[s2], bb.x, bb.y);
      mma16816(C2b[j2], A2l1[s2], bb.x, bb.y);
      mma16816(C2a[j2], A2h0[s2], bb.z, bb.w);
      mma16816(C2b[j2], A2h1[s2], bb.z, bb.w);
    }
  }
  // ---- bias ----
  const float* b2f = B2s + f * 32;
#pragma unroll
  for (int j2 = 0; j2 < 4; j2++) {
    float2 b = *(const float2*)(b2f + 8 * j2 + 2 * t);
    C2a[j2][0] += b.x; C2a[j2][1] += b.y; C2a[j2][2] += b.x; C2a[j2][3] += b.y;
    C2b[j2][0] += b.x; C2b[j2][1] += b.y; C2b[j2][2] += b.x; C2b[j2][3] += b.y;
  }
  // ---- epilogues (proven scatter) ----
  if (!vec) {
    epi_plain(C2a, g, t, outp, rowbase);
    epi_plain(C2b, g, t, outp, rowbase + 64);
  } else {
    epi_vec(C2a, ub, ro, g, t, outp, rowbase);
    epi_vec(C2b, ub, ro + 64, g, t, outp, rowbase + 64);
  }
}

// load x rows into A fragments (hi/lo bf16) for one 16-row slice
__device__ __forceinline__ void load_xfrags(const float* __restrict__ x, int row0,
                                            int ro, int t,
                                            uint32_t (&Ah)[4][4], uint32_t (&Al)[4][4]) {
  const float* base = x + (size_t)(row0 + ro) * 64 + 2 * t;
#pragma unroll
  for (int s = 0; s < 4; s++) {
    const float* bs = base + 16 * s;
    float2 v0 = __ldg((const float2*)(bs));
    float2 v1 = __ldg((const float2*)(bs + 8 * 64));
    float2 v2 = __ldg((const float2*)(bs + 8));
    float2 v3 = __ldg((const float2*)(bs + 8 * 64 + 8));
    Ah[s][0] = pack_split(v0.x, v0.y, Al[s][0]);
    Ah[s][1] = pack_split(v1.x, v1.y, Al[s][1]);
    Ah[s][2] = pack_split(v2.x, v2.y, Al[s][2]);
    Ah[s][3] = pack_split(v3.x, v3.y, Al[s][3]);
  }
}

__global__ void __launch_bounds__(NTH) conv_mma(Params p) {
  extern __shared__ char sm[];
  uint32_t* SB1 = (uint32_t*)(sm + OFF_SB1);
  uint32_t* SB2 = (uint32_t*)(sm + OFF_SB2);
  float* B1s = (float*)(sm + OFF_B1);
  float* B2s = (float*)(sm + OFF_B2);
  float* U   = (float*)(sm + OFF_U);

  const int tid = threadIdx.x;

  // ---- one-time: build B fragments, hi/lo interleaved per lane (LDS.128) ----
  // filter order: 0=f0 (w[0..3]), 1=f11 (w[8..11]), 2=f10 (w[4..7])
  for (int idx = tid; idx < 12288; idx += NTH) {
    int i = idx;
    int q = i & 3; i >>= 2;
    int lane = i & 31; i >>= 5;
    int s = i & 3; i >>= 2;
    int j = i & 7; i >>= 3;
    int f = i;
    int half = q >> 1, r = q & 1;
    int g = lane >> 2, t = lane & 3;
    int n = 8 * j + g;
    int kb = 16 * s + 2 * t + 8 * r;
    const float* w1 = (f == 0) ? p.w[0] : (f == 1) ? p.w[8] : p.w[4];
    float v0 = __ldg(w1 + kb * 64 + n);
    float v1 = __ldg(w1 + (kb + 1) * 64 + n);
    __nv_bfloat162 pk;
    pk.x = bf_part(v0, half);
    pk.y = bf_part(v1, half);
    SB1[idx] = *reinterpret_cast<uint32_t*>(&pk);
  }
  for (int idx = tid; idx < 6144; idx += NTH) {
    int i = idx;
    int q = i & 3; i >>= 2;
    int lane = i & 31; i >>= 5;
    int s = i & 3; i >>= 2;
    int j = i & 3; i >>= 2;
    int f = i;
    int half = q >> 1, r = q & 1;
    int g = lane >> 2, t = lane & 3;
    int n = 8 * j + g;
    int kb = 16 * s + 2 * t + 8 * r;
    const float* w2 = (f == 0) ? p.w[2] : (f == 1) ? p.w[10] : p.w[6];
    float v0 = __ldg(w2 + kb * 32 + n);
    float v1 = __ldg(w2 + (kb + 1) * 32 + n);
    __nv_bfloat162 pk;
    pk.x = bf_part(v0, half);
    pk.y = bf_part(v1, half);
    SB2[idx] = *reinterpret_cast<uint32_t*>(&pk);
  }
  for (int n = tid; n < 192; n += NTH) {
    const float* b1 = (n < 64) ? p.w[1] : (n < 128) ? p.w[9] : p.w[5];
    B1s[n] = __ldg(b1 + (n & 63));
  }
  for (int n = tid; n < 96; n += NTH) {
    const float* b2 = (n < 32) ? p.w[3] : (n < 64) ? p.w[11] : p.w[7];
    B2s[n] = __ldg(b2 + (n & 31));
  }
  __syncthreads();

  const int w = tid >> 5, lane = tid & 31;
  const int g = lane >> 2, t = lane & 3;
  const int ro = w * 16 + g;            // slice a; slice b = ro + 64
  const uint32_t* sb1l4 = SB1 + lane * 4;
  const uint32_t* sb2l4 = SB2 + lane * 4;

  float* const o0a = p.out;
  float* const o0b = p.out + (size_t)32 * MROWS;
  float* const o1a = p.out + (size_t)64 * MROWS;
  float* const o1b = p.out + (size_t)160 * MROWS;
  float* const o1c = p.out + (size_t)256 * MROWS;

  for (int tile = blockIdx.x; tile < NTILES; tile += GRID) {
    const int row0 = tile << 7;
    float* ubuf = U + (size_t)(tile & 1) * 512;
    {
      const float* rp = p.rij + (size_t)(row0 + tid) * 3;
      float r0 = rp[0], r1 = rp[1], r2 = rp[2];
      float d2 = r0 * r0 + r1 * r1 + r2 * r2;
      float dij = sqrtf(d2);
      float nrm = sqrtf(fmaxf(d2, 1e-8f));
      float* uu = ubuf + tid * 4;
      if (dij < 1e-8f) { uu[0] = 0.f; uu[1] = 0.f; uu[2] = 0.f; }
      else { uu[0] = r0 / nrm; uu[1] = r1 / nrm; uu[2] = r2 / nrm; }
    }
    __syncthreads();

    uint32_t Ah0[4][4], Al0[4][4], Ah1[4][4], Al1[4][4];
    const int rowbase = row0 + w * 16;

    // x0: f0 -> out0_a (plain), f11 -> out1_a (vec)
    load_xfrags(p.x0, row0, ro, t, Ah0, Al0);
    load_xfrags(p.x0, row0, ro + 64, t, Ah1, Al1);
    run_pair(Ah0, Al0, Ah1, Al1, 0, sb1l4, sb2l4, B1s, B2s, ubuf, ro, g, t, o0a, rowbase, false);
    run_pair(Ah0, Al0, Ah1, Al1, 1, sb1l4, sb2l4, B1s, B2s, ubuf, ro, g, t, o1a, rowbase, true);

    // x1: f0 -> out0_b (plain), f10 -> out1_b (vec), f11 -> out1_c (vec)
    load_xfrags(p.x1, row0, ro, t, Ah0, Al0);
    load_xfrags(p.x1, row0, ro + 64, t, Ah1, Al1);
    run_pair(Ah0, Al0, Ah1, Al1, 0, sb1l4, sb2l4, B1s, B2s, ubuf, ro, g, t, o0b, rowbase, false);
    run_pair(Ah0, Al0, Ah1, Al1, 2, sb1l4, sb2l4, B1s, B2s, ubuf, ro, g, t, o1b, rowbase, true);
    run_pair(Ah0, Al0, Ah1, Al1, 1, sb1l4, sb2l4, B1s, B2s, ubuf, ro, g, t, o1c, rowbase, true);
  }
}

extern "C" void kernel_launch(void* const* d_in, const int* in_sizes, int n_in,
                              void* d_out, int out_size) {
  Params p;
  p.x0  = (const float*)d_in[0];
  p.x1  = (const float*)d_in[1];
  // d_in[2] = rbf: unused by the reference computation
  p.rij = (const float*)d_in[3];
  for (int i = 0; i < 12; i++) p.w[i] = (const float*)d_in[4 + i];
  p.out = (float*)d_out;

  cudaFuncSetAttribute(conv_mma, cudaFuncAttributeMaxDynamicSharedMemorySize, SMEM_BYTES);
  conv_mma<<<GRID, NTH, SMEM_BYTES>>>(p);
}

// round 10
// speedup vs baseline: 3.9664x; 1.0218x over previous
#include <cuda_runtime.h>
#include <cuda_bf16.h>
#include <cstdint>
#include <cstddef>

#define MROWS (512*512)
#define NTILES 2048
#define GRID 296
#define NTH 128

// ---------------- smem layout (bytes) ----------------
// SB1: stage-1 B fragments uint32[3 f][8 j][4 s][32 lane][4 q]  q={hi0,hi1,lo0,lo1}
// SB2: stage-2 B fragments uint32[3][4][4][32][4]
// B1S/B2S: biases. U: unit vectors double-buffered [2][128][4].
#define OFF_SB1 0u
#define OFF_SB2 49152u
#define OFF_B1  73728u
#define OFF_B2  74496u
#define OFF_U   74880u
#define SMEM_BYTES 78976u

struct Params {
  const float* x0;
  const float* x1;
  const float* rij;
  const float* w[12];   // f0: w1,b1,w2,b2 ; f10: ... ; f11: ...
  float* out;
};

__device__ __forceinline__ void mma16816(float (&c)[4], const uint32_t (&a)[4],
                                         uint32_t b0, uint32_t b1) {
  asm volatile(
      "mma.sync.aligned.m16n8k16.row.col.f32.bf16.bf16.f32 "
      "{%0,%1,%2,%3}, {%4,%5,%6,%7}, {%8,%9}, {%0,%1,%2,%3};"
      : "+f"(c[0]), "+f"(c[1]), "+f"(c[2]), "+f"(c[3])
      : "r"(a[0]), "r"(a[1]), "r"(a[2]), "r"(a[3]), "r"(b0), "r"(b1));
}

__device__ __forceinline__ uint32_t pack_split(float vx, float vy, uint32_t& lo) {
  __nv_bfloat162 h = __float22bfloat162_rn(make_float2(vx, vy));
  float2 hf = __bfloat1622float2(h);
  __nv_bfloat162 l = __float22bfloat162_rn(make_float2(vx - hf.x, vy - hf.y));
  lo = *reinterpret_cast<uint32_t*>(&l);
  return *reinterpret_cast<uint32_t*>(&h);
}

__device__ __forceinline__ __nv_bfloat16 bf_part(float v, int h) {
  __nv_bfloat16 hi = __float2bfloat16_rn(v);
  if (h == 0) return hi;
  return __float2bfloat16_rn(v - __bfloat162float(hi));
}

// ---- proven scatter epilogues (unchanged from round 8) ----
__device__ __forceinline__ void epi_plain(const float (&C2)[4][4], int g, int t,
                                          float* __restrict__ outp, int rowbase) {
  float* r0p = outp + (size_t)(rowbase + g) * 32;
  float* r1p = outp + (size_t)(rowbase + g + 8) * 32;
#pragma unroll
  for (int j2 = 0; j2 < 4; j2++) {
    int col = 8 * j2 + 2 * t;
    *(float2*)(r0p + col) = make_float2(C2[j2][0], C2[j2][1]);
    *(float2*)(r1p + col) = make_float2(C2[j2][2], C2[j2][3]);
  }
}

__device__ __forceinline__ void epi_vec(const float (&C2)[4][4],
                                        const float* __restrict__ ub,
                                        int ro, int g, int t,
                                        float* __restrict__ outp, int rowbase) {
  const float* u0p = ub + ro * 4;
  const float* u1p = ub + (ro + 8) * 4;
  float ua0 = u0p[0], ua1 = u0p[1], ua2 = u0p[2];
  float ub0 = u1p[0], ub1 = u1p[1], ub2 = u1p[2];
  float* r0p = outp + (size_t)(rowbase + g) * 96;
  float* r1p = outp + (size_t)(rowbase + g + 8) * 96;
#pragma unroll
  for (int j2 = 0; j2 < 4; j2++) {
    int col3 = (8 * j2 + 2 * t) * 3;
    float v0 = C2[j2][0], v1 = C2[j2][1];
    r0p[col3 + 0] = v0 * ua0; r0p[col3 + 1] = v0 * ua1; r0p[col3 + 2] = v0 * ua2;
    r0p[col3 + 3] = v1 * ua0; r0p[col3 + 4] = v1 * ua1; r0p[col3 + 5] = v1 * ua2;
    float w0 = C2[j2][2], w1 = C2[j2][3];
    r1p[col3 + 0] = w0 * ub0; r1p[col3 + 1] = w0 * ub1; r1p[col3 + 2] = w0 * ub2;
    r1p[col3 + 3] = w1 * ub0; r1p[col3 + 4] = w1 * ub1; r1p[col3 + 5] = w1 * ub2;
  }
}

// bias+relu -> stage-2 A frags -> GEMM2 -> bias -> epilogue, for ONE slice.
// Only one slice's A2/C2 registers live at a time (round-8 had both slices'
// stage-2 state live simultaneously -> 255-reg cap -> spills).
__device__ __forceinline__ void stage2_epi(
    float (&C1)[8][4], int f,
    const uint32_t* __restrict__ sb2l4,
    const float* __restrict__ B1s, const float* __restrict__ B2s,
    const float* __restrict__ ub, int ro, int g, int t,
    float* __restrict__ outp, int rowbase, bool vec) {
  // ---- bias + relu ----
  const float* b1f = B1s + f * 64;
#pragma unroll
  for (int j = 0; j < 8; j++) {
    float2 b = *(const float2*)(b1f + 8 * j + 2 * t);
    C1[j][0] = fmaxf(C1[j][0] + b.x, 0.f);
    C1[j][1] = fmaxf(C1[j][1] + b.y, 0.f);
    C1[j][2] = fmaxf(C1[j][2] + b.x, 0.f);
    C1[j][3] = fmaxf(C1[j][3] + b.y, 0.f);
  }
  // ---- C1 -> stage-2 A fragments (register-only) ----
  uint32_t A2h[4][4], A2l[4][4];
#pragma unroll
  for (int s2 = 0; s2 < 4; s2++) {
    A2h[s2][0] = pack_split(C1[2 * s2][0],     C1[2 * s2][1],     A2l[s2][0]);
    A2h[s2][1] = pack_split(C1[2 * s2][2],     C1[2 * s2][3],     A2l[s2][1]);
    A2h[s2][2] = pack_split(C1[2 * s2 + 1][0], C1[2 * s2 + 1][1], A2l[s2][2]);
    A2h[s2][3] = pack_split(C1[2 * s2 + 1][2], C1[2 * s2 + 1][3], A2l[s2][3]);
  }
  // ---- stage 2 (same j2-outer order as round 8) ----
  float C2[4][4];
#pragma unroll
  for (int j = 0; j < 4; j++)
#pragma unroll
    for (int e = 0; e < 4; e++) C2[j][e] = 0.f;
#pragma unroll
  for (int j2 = 0; j2 < 4; j2++) {
#pragma unroll
    for (int s2 = 0; s2 < 4; s2++) {
      uint4 bb = *(const uint4*)(sb2l4 + ((f * 4 + j2) * 4 + s2) * 128);
      mma16816(C2[j2], A2h[s2], bb.x, bb.y);
      mma16816(C2[j2], A2l[s2], bb.x, bb.y);
      mma16816(C2[j2], A2h[s2], bb.z, bb.w);
    }
  }
  // ---- bias ----
  const float* b2f = B2s + f * 32;
#pragma unroll
  for (int j2 = 0; j2 < 4; j2++) {
    float2 b = *(const float2*)(b2f + 8 * j2 + 2 * t);
    C2[j2][0] += b.x; C2[j2][1] += b.y;
    C2[j2][2] += b.x; C2[j2][3] += b.y;
  }
  if (vec) epi_vec(C2, ub, ro, g, t, outp, rowbase);
  else     epi_plain(C2, g, t, outp, rowbase);
}

// dual-slice stage 1 (shared B loads, 2x ILP) -> sequential per-slice stage 2.
__device__ __forceinline__ void run_pair(
    const uint32_t (&Ah0)[4][4], const uint32_t (&Al0)[4][4],
    const uint32_t (&Ah1)[4][4], const uint32_t (&Al1)[4][4], int f,
    const uint32_t* __restrict__ sb1l4, const uint32_t* __restrict__ sb2l4,
    const float* __restrict__ B1s, const float* __restrict__ B2s,
    const float* __restrict__ ub, int ro, int g, int t,
    float* __restrict__ outp, int rowbase, bool vec) {
  float C1a[8][4], C1b[8][4];
#pragma unroll
  for (int j = 0; j < 8; j++)
#pragma unroll
    for (int e = 0; e < 4; e++) { C1a[j][e] = 0.f; C1b[j][e] = 0.f; }
#pragma unroll
  for (int j = 0; j < 8; j++) {
#pragma unroll
    for (int s = 0; s < 4; s++) {
      uint4 bb = *(const uint4*)(sb1l4 + ((f * 8 + j) * 4 + s) * 128);
      mma16816(C1a[j], Ah0[s], bb.x, bb.y);
      mma16816(C1b[j], Ah1[s], bb.x, bb.y);
      mma16816(C1a[j], Al0[s], bb.x, bb.y);
      mma16816(C1b[j], Al1[s], bb.x, bb.y);
      mma16816(C1a[j], Ah0[s], bb.z, bb.w);
      mma16816(C1b[j], Ah1[s], bb.z, bb.w);
    }
  }
  stage2_epi(C1a, f, sb2l4, B1s, B2s, ub, ro,      g, t, outp, rowbase,      vec);
  stage2_epi(C1b, f, sb2l4, B1s, B2s, ub, ro + 64, g, t, outp, rowbase + 64, vec);
}

// load x rows into A fragments (hi/lo bf16) for one 16-row slice
__device__ __forceinline__ void load_xfrags(const float* __restrict__ x, int row0,
                                            int ro, int t,
                                            uint32_t (&Ah)[4][4], uint32_t (&Al)[4][4]) {
  const float* base = x + (size_t)(row0 + ro) * 64 + 2 * t;
#pragma unroll
  for (int s = 0; s < 4; s++) {
    const float* bs = base + 16 * s;
    float2 v0 = __ldg((const float2*)(bs));
    float2 v1 = __ldg((const float2*)(bs + 8 * 64));
    float2 v2 = __ldg((const float2*)(bs + 8));
    float2 v3 = __ldg((const float2*)(bs + 8 * 64 + 8));
    Ah[s][0] = pack_split(v0.x, v0.y, Al[s][0]);
    Ah[s][1] = pack_split(v1.x, v1.y, Al[s][1]);
    Ah[s][2] = pack_split(v2.x, v2.y, Al[s][2]);
    Ah[s][3] = pack_split(v3.x, v3.y, Al[s][3]);
  }
}

__global__ void __launch_bounds__(NTH) conv_mma(Params p) {
  extern __shared__ char sm[];
  uint32_t* SB1 = (uint32_t*)(sm + OFF_SB1);
  uint32_t* SB2 = (uint32_t*)(sm + OFF_SB2);
  float* B1s = (float*)(sm + OFF_B1);
  float* B2s = (float*)(sm + OFF_B2);
  float* U   = (float*)(sm + OFF_U);

  const int tid = threadIdx.x;

  // ---- one-time: build B fragments, hi/lo interleaved per lane (LDS.128) ----
  // filter order: 0=f0 (w[0..3]), 1=f11 (w[8..11]), 2=f10 (w[4..7])
  for (int idx = tid; idx < 12288; idx += NTH) {
    int i = idx;
    int q = i & 3; i >>= 2;
    int lane = i & 31; i >>= 5;
    int s = i & 3; i >>= 2;
    int j = i & 7; i >>= 3;
    int f = i;
    int half = q >> 1, r = q & 1;
    int g = lane >> 2, t = lane & 3;
    int n = 8 * j + g;
    int kb = 16 * s + 2 * t + 8 * r;
    const float* w1 = (f == 0) ? p.w[0] : (f == 1) ? p.w[8] : p.w[4];
    float v0 = __ldg(w1 + kb * 64 + n);
    float v1 = __ldg(w1 + (kb + 1) * 64 + n);
    __nv_bfloat162 pk;
    pk.x = bf_part(v0, half);
    pk.y = bf_part(v1, half);
    SB1[idx] = *reinterpret_cast<uint32_t*>(&pk);
  }
  for (int idx = tid; idx < 6144; idx += NTH) {
    int i = idx;
    int q = i & 3; i >>= 2;
    int lane = i & 31; i >>= 5;
    int s = i & 3; i >>= 2;
    int j = i & 3; i >>= 2;
    int f = i;
    int half = q >> 1, r = q & 1;
    int g = lane >> 2, t = lane & 3;
    int n = 8 * j + g;
    int kb = 16 * s + 2 * t + 8 * r;
    const float* w2 = (f == 0) ? p.w[2] : (f == 1) ? p.w[10] : p.w[6];
    float v0 = __ldg(w2 + kb * 32 + n);
    float v1 = __ldg(w2 + (kb + 1) * 32 + n);
    __nv_bfloat162 pk;
    pk.x = bf_part(v0, half);
    pk.y = bf_part(v1, half);
    SB2[idx] = *reinterpret_cast<uint32_t*>(&pk);
  }
  for (int n = tid; n < 192; n += NTH) {
    const float* b1 = (n < 64) ? p.w[1] : (n < 128) ? p.w[9] : p.w[5];
    B1s[n] = __ldg(b1 + (n & 63));
  }
  for (int n = tid; n < 96; n += NTH) {
    const float* b2 = (n < 32) ? p.w[3] : (n < 64) ? p.w[11] : p.w[7];
    B2s[n] = __ldg(b2 + (n & 31));
  }
  __syncthreads();

  const int w = tid >> 5, lane = tid & 31;
  const int g = lane >> 2, t = lane & 3;
  const int ro = w * 16 + g;            // slice a; slice b = ro + 64
  const uint32_t* sb1l4 = SB1 + lane * 4;
  const uint32_t* sb2l4 = SB2 + lane * 4;

  float* const o0a = p.out;
  float* const o0b = p.out + (size_t)32 * MROWS;
  float* const o1a = p.out + (size_t)64 * MROWS;
  float* const o1b = p.out + (size_t)160 * MROWS;
  float* const o1c = p.out + (size_t)256 * MROWS;

  for (int tile = blockIdx.x; tile < NTILES; tile += GRID) {
    const int row0 = tile << 7;
    float* ubuf = U + (size_t)(tile & 1) * 512;
    {
      const float* rp = p.rij + (size_t)(row0 + tid) * 3;
      float r0 = rp[0], r1 = rp[1], r2 = rp[2];
      float d2 = r0 * r0 + r1 * r1 + r2 * r2;
      float dij = sqrtf(d2);
      float nrm = sqrtf(fmaxf(d2, 1e-8f));
      float* uu = ubuf + tid * 4;
      if (dij < 1e-8f) { uu[0] = 0.f; uu[1] = 0.f; uu[2] = 0.f; }
      else { uu[0] = r0 / nrm; uu[1] = r1 / nrm; uu[2] = r2 / nrm; }
    }
    __syncthreads();

    uint32_t Ah0[4][4], Al0[4][4], Ah1[4][4], Al1[4][4];
    const int rowbase = row0 + w * 16;

    // x0: f0 -> out0_a (plain), f11 -> out1_a (vec)
    load_xfrags(p.x0, row0, ro, t, Ah0, Al0);
    load_xfrags(p.x0, row0, ro + 64, t, Ah1, Al1);
    run_pair(Ah0, Al0, Ah1, Al1, 0, sb1l4, sb2l4, B1s, B2s, ubuf, ro, g, t, o0a, rowbase, false);
    run_pair(Ah0, Al0, Ah1, Al1, 1, sb1l4, sb2l4, B1s, B2s, ubuf, ro, g, t, o1a, rowbase, true);

    // x1: f0 -> out0_b (plain), f10 -> out1_b (vec), f11 -> out1_c (vec)
    load_xfrags(p.x1, row0, ro, t, Ah0, Al0);
    load_xfrags(p.x1, row0, ro + 64, t, Ah1, Al1);
    run_pair(Ah0, Al0, Ah1, Al1, 0, sb1l4, sb2l4, B1s, B2s, ubuf, ro, g, t, o0b, rowbase, false);
    run_pair(Ah0, Al0, Ah1, Al1, 2, sb1l4, sb2l4, B1s, B2s, ubuf, ro, g, t, o1b, rowbase, true);
    run_pair(Ah0, Al0, Ah1, Al1, 1, sb1l4, sb2l4, B1s, B2s, ubuf, ro, g, t, o1c, rowbase, true);
  }
}

extern "C" void kernel_launch(void* const* d_in, const int* in_sizes, int n_in,
                              void* d_out, int out_size) {
  Params p;
  p.x0  = (const float*)d_in[0];
  p.x1  = (const float*)d_in[1];
  // d_in[2] = rbf: unused by the reference computation
  p.rij = (const float*)d_in[3];
  for (int i = 0; i < 12; i++) p.w[i] = (const float*)d_in[4 + i];
  p.out = (float*)d_out;

  cudaFuncSetAttribute(conv_mma, cudaFuncAttributeMaxDynamicSharedMemorySize, SMEM_BYTES);
  conv_mma<<<GRID, NTH, SMEM_BYTES>>>(p);
}